// round 1
// baseline (speedup 1.0000x reference)
#include <cuda_runtime.h>
#include <math.h>

#define NN   50000
#define NE   800000
#define IND  256
#define HID  128
#define OUTD 64
#define NB   4096
#define BN_EPS 1e-5f
#define SLOPE  0.01f

// ---------------- scratch (device globals; no allocation allowed) ----------
__device__ float g_deg[NN];                    // degree, then dinv in-place
__device__ float g_s  [(size_t)NN * HID];      // dinv-scaled linear output
__device__ float g_acc[(size_t)NN * HID];      // aggregation accumulator / post-relu
__device__ float g_emb[3][(size_t)NN * HID];   // per-layer BN outputs
__device__ float g_stats[2 * HID];             // column sum / sumsq

// ---------------- degree / dinv --------------------------------------------
__global__ void k_deg_init() {
    int i = blockIdx.x * blockDim.x + threadIdx.x;
    if (i < NN) g_deg[i] = 1.0f;               // self-loop
}
__global__ void k_deg_count(const int* __restrict__ dst) {
    int e = blockIdx.x * blockDim.x + threadIdx.x;
    if (e < NE) atomicAdd(&g_deg[dst[e]], 1.0f);
}
__global__ void k_dinv() {
    int i = blockIdx.x * blockDim.x + threadIdx.x;
    if (i < NN) g_deg[i] = rsqrtf(g_deg[i]);
}
__global__ void k_zero_stats() {
    int i = threadIdx.x;
    if (i < 2 * HID) g_stats[i] = 0.0f;
}

// ---------------- GEMM: out[m][n] = dinv[m] * sum_k X[m][k] * W[n][k] -------
// BM=32 rows, all 128 cols per block; 256 threads; each thread 4x4 outputs.
template <int K>
__global__ void k_gemm(const float* __restrict__ X, const float* __restrict__ W) {
    __shared__ float As[32][33];
    __shared__ float Bs[32][132];              // [kk][n], padded row (16B-aligned stride)

    const int t  = threadIdx.x;
    const int m0 = blockIdx.x * 32;
    const int ry = t >> 5;                     // 0..7 -> row group
    const int cx = t & 31;                     // 0..31 -> col group (4 cols)

    float acc[4][4] = {};

    for (int k0 = 0; k0 < K; k0 += 32) {
        // load A tile 32x32 (coalesced)
        {
            int r = t >> 5, kk = t & 31;
            #pragma unroll
            for (int i = 0; i < 4; i++) {
                int rr = r + i * 8;
                int m  = m0 + rr;
                As[rr][kk] = (m < NN) ? X[(size_t)m * K + k0 + kk] : 0.0f;
            }
        }
        // load B tile: Bs[kk][n] = W[n*K + k0+kk]   (128x32, coalesced on k)
        {
            int kk = t & 31, n0 = t >> 5;
            #pragma unroll
            for (int i = 0; i < 16; i++) {
                int n = n0 + i * 8;
                Bs[kk][n] = W[(size_t)n * K + k0 + kk];
            }
        }
        __syncthreads();

        #pragma unroll
        for (int kk = 0; kk < 32; kk++) {
            float4 b = *(const float4*)&Bs[kk][cx * 4];
            #pragma unroll
            for (int i = 0; i < 4; i++) {
                float a = As[ry * 4 + i][kk];
                acc[i][0] += a * b.x;
                acc[i][1] += a * b.y;
                acc[i][2] += a * b.z;
                acc[i][3] += a * b.w;
            }
        }
        __syncthreads();
    }

    #pragma unroll
    for (int i = 0; i < 4; i++) {
        int m = m0 + ry * 4 + i;
        if (m < NN) {
            float d = g_deg[m];                // dinv
            float4 v = make_float4(acc[i][0] * d, acc[i][1] * d,
                                   acc[i][2] * d, acc[i][3] * d);
            *(float4*)&g_s  [(size_t)m * HID + cx * 4] = v;
            *(float4*)&g_acc[(size_t)m * HID + cx * 4] = v;   // self-loop term
        }
    }
}

// ---------------- edge scatter: acc[dst] += s[src], one warp per edge -------
__global__ void k_edge(const int* __restrict__ src, const int* __restrict__ dst) {
    int t = blockIdx.x * blockDim.x + threadIdx.x;   // NE*32 threads total
    int e = t >> 5;
    int c = t & 31;                                  // float4 chunk 0..31
    if (e >= NE) return;
    int u = src[e];
    int v = dst[e];
    float4 val = *(const float4*)(g_s + (size_t)u * HID + c * 4);
    atomicAdd((float4*)(g_acc + (size_t)v * HID + c * 4), val);
}

// ---------------- finish: v = acc*dinv + b, relu; column sum/sumsq ----------
__global__ void k_finish(const float* __restrict__ bias) {
    int c  = threadIdx.x;                      // 128 threads = 128 cols
    int r0 = blockIdx.x * 64;
    float bc = bias[c];
    float sum = 0.0f, sq = 0.0f;
    for (int i = 0; i < 64; i++) {
        int r = r0 + i;
        if (r >= NN) break;
        float v = g_acc[(size_t)r * HID + c] * g_deg[r] + bc;
        v = fmaxf(v, 0.0f);
        g_acc[(size_t)r * HID + c] = v;
        sum += v;
        sq  += v * v;
    }
    atomicAdd(&g_stats[c],       sum);
    atomicAdd(&g_stats[HID + c], sq);
}

// ---------------- batchnorm normalize -> emb[l] -----------------------------
__global__ void k_bn(const float* __restrict__ gamma, const float* __restrict__ beta,
                     float* __restrict__ emb) {
    int idx = blockIdx.x * blockDim.x + threadIdx.x;
    if (idx >= NN * HID) return;
    int   c    = idx & (HID - 1);
    float mean = g_stats[c] * (1.0f / NN);
    float var  = g_stats[HID + c] * (1.0f / NN) - mean * mean;
    float v    = (g_acc[idx] - mean) * rsqrtf(var + BN_EPS) * gamma[c] + beta[c];
    emb[idx] = v;
}

// ---------------- attention pooling + output projection ---------------------
// One block (128 threads) per output row. Row groups:
//   [0,4096): z_D[drug_pos]  [4096,8192): z_T[target_pos]
//   [8192,12288): z_D[drug_neg]  [12288,16384): z_T[target_neg]
__global__ void k_att(const int* __restrict__ dp, const int* __restrict__ tp,
                      const int* __restrict__ dn, const int* __restrict__ tn,
                      const float* __restrict__ WD, const float* __restrict__ WT,
                      const float* __restrict__ qD, const float* __restrict__ qT,
                      const float* __restrict__ ow, const float* __restrict__ ob,
                      float* __restrict__ out) {
    int row = blockIdx.x;
    int grp = row >> 12;
    int j   = row & 4095;

    int node;
    const float *W, *q;
    if      (grp == 0) { node = dp[j]; W = WD; q = qD; }
    else if (grp == 1) { node = tp[j]; W = WT; q = qT; }
    else if (grp == 2) { node = dn[j]; W = WD; q = qD; }
    else               { node = tn[j]; W = WT; q = qT; }

    __shared__ float se[3][HID];
    __shared__ float red3[3][HID];
    __shared__ float alpha[3];
    __shared__ float pooled[HID];

    int t = threadIdx.x;   // 128
    #pragma unroll
    for (int l = 0; l < 3; l++)
        se[l][t] = g_emb[l][(size_t)node * HID + t];
    __syncthreads();

    // h_att[l][t] = leaky_relu(dot(emb_l, W[t,:])); pe[l] = h_att * q[t]
    float qk = q[t];
    const float* wrow = W + (size_t)t * HID;
    float pe[3];
    #pragma unroll
    for (int l = 0; l < 3; l++) {
        float h = 0.0f;
        #pragma unroll 8
        for (int k = 0; k < HID; k++) h += se[l][k] * wrow[k];
        h = (h > 0.0f) ? h : SLOPE * h;
        pe[l] = h * qk;
    }
    #pragma unroll
    for (int l = 0; l < 3; l++) red3[l][t] = pe[l];
    __syncthreads();
    for (int sft = 64; sft >= 1; sft >>= 1) {
        if (t < sft) {
            #pragma unroll
            for (int l = 0; l < 3; l++) red3[l][t] += red3[l][t + sft];
        }
        __syncthreads();
    }
    if (t == 0) {
        float e0 = red3[0][0], e1 = red3[1][0], e2 = red3[2][0];
        float m  = fmaxf(e0, fmaxf(e1, e2));
        float a0 = expf(e0 - m), a1 = expf(e1 - m), a2 = expf(e2 - m);
        float s  = a0 + a1 + a2;
        alpha[0] = a0 / s; alpha[1] = a1 / s; alpha[2] = a2 / s;
    }
    __syncthreads();
    pooled[t] = alpha[0] * se[0][t] + alpha[1] * se[1][t] + alpha[2] * se[2][t];
    __syncthreads();

    if (t < OUTD) {
        float z = ob[t];
        const float* orow = ow + (size_t)t * HID;
        #pragma unroll 8
        for (int k = 0; k < HID; k++) z += pooled[k] * orow[k];
        out[(size_t)row * OUTD + t] = z;
    }
}

// ---------------- launch -----------------------------------------------------
extern "C" void kernel_launch(void* const* d_in, const int* in_sizes, int n_in,
                              void* d_out, int out_size) {
    const float* x     = (const float*)d_in[0];
    const int*   ei    = (const int*)  d_in[1];
    const int*   dp    = (const int*)  d_in[2];
    const int*   tp    = (const int*)  d_in[3];
    const int*   dn    = (const int*)  d_in[4];
    const int*   tn    = (const int*)  d_in[5];
    // d_in[6] = adjacency_matrix (dead)
    const float* w0    = (const float*)d_in[7];
    const float* b0    = (const float*)d_in[8];
    const float* w1    = (const float*)d_in[9];
    const float* b1    = (const float*)d_in[10];
    const float* w2    = (const float*)d_in[11];
    const float* b2    = (const float*)d_in[12];
    const float* gamma = (const float*)d_in[13];
    const float* beta  = (const float*)d_in[14];
    const float* WD    = (const float*)d_in[15];
    const float* WT    = (const float*)d_in[16];
    const float* qD    = (const float*)d_in[17];
    const float* qT    = (const float*)d_in[18];
    const float* ow    = (const float*)d_in[19];
    const float* ob    = (const float*)d_in[20];
    float*       out   = (float*)d_out;

    const int* src = ei;
    const int* dst = ei + NE;

    float* embBase = nullptr;
    cudaGetSymbolAddress((void**)&embBase, g_emb);

    k_deg_init <<<(NN + 255) / 256, 256>>>();
    k_deg_count<<<(NE + 255) / 256, 256>>>(dst);
    k_dinv     <<<(NN + 255) / 256, 256>>>();

    const int GEMM_BLOCKS = (NN + 31) / 32;          // 1563
    const int EDGE_BLOCKS = (NE * 32) / 256;         // 100000 (exact)

    const float* ws[3] = {w0, w1, w2};
    const float* bs[3] = {b0, b1, b2};

    for (int l = 0; l < 3; l++) {
        k_zero_stats<<<1, 256>>>();
        if (l == 0)
            k_gemm<IND><<<GEMM_BLOCKS, 256>>>(x, ws[0]);
        else
            k_gemm<HID><<<GEMM_BLOCKS, 256>>>(embBase + (size_t)(l - 1) * NN * HID, ws[l]);
        k_edge  <<<EDGE_BLOCKS, 256>>>(src, dst);
        k_finish<<<(NN + 63) / 64, 128>>>(bs[l]);
        k_bn    <<<(NN * HID + 255) / 256, 256>>>(gamma, beta,
                                                  embBase + (size_t)l * NN * HID);
    }

    k_att<<<4 * NB, 128>>>(dp, tp, dn, tn, WD, WT, qD, qT, ow, ob, out);
}

// round 2
// speedup vs baseline: 6.1962x; 6.1962x over previous
#include <cuda_runtime.h>
#include <math.h>

#define NN   50000
#define NE   800000
#define IND  256
#define HID  128
#define OUTD 64
#define NB   4096
#define BN_EPS 1e-5f
#define SLOPE  0.01f

// ---------------- scratch (device globals; no allocation allowed) ----------
__device__ float g_deg [NN];                    // dinv
__device__ int   g_degi[NN];                    // int degree (no self loop)
__device__ int   g_off [NN];                    // CSR offsets
__device__ int   g_cnt [NN];                    // scatter counters
__device__ int   g_ssrc[NE];                    // src ids sorted by dst
__device__ float g_s   [(size_t)NN * HID];      // dinv-scaled linear output
__device__ float g_acc [(size_t)NN * HID];      // aggregation result / post-relu
__device__ float g_emb [3][(size_t)NN * HID];   // per-layer BN outputs
__device__ float g_stats[2 * HID];              // column sum / sumsq

// ---------------- init / degree / dinv --------------------------------------
__global__ void k_init() {
    int i = blockIdx.x * blockDim.x + threadIdx.x;
    if (i < NN) { g_degi[i] = 0; g_cnt[i] = 0; }
}
__global__ void k_deg_count(const int* __restrict__ dst) {
    int e = blockIdx.x * blockDim.x + threadIdx.x;
    if (e < NE) atomicAdd(&g_degi[dst[e]], 1);
}
__global__ void k_scan() {                      // 1 block, 1024 threads
    const int PER = (NN + 1023) / 1024;         // 49
    int t = threadIdx.x;
    int base = t * PER;
    int sum = 0;
    for (int j = 0; j < PER; j++) { int i = base + j; if (i < NN) sum += g_degi[i]; }
    __shared__ int tmp[1024];
    tmp[t] = sum;
    __syncthreads();
    for (int d = 1; d < 1024; d <<= 1) {
        int v = (t >= d) ? tmp[t - d] : 0;
        __syncthreads();
        tmp[t] += v;
        __syncthreads();
    }
    int off = (t == 0) ? 0 : tmp[t - 1];
    for (int j = 0; j < PER; j++) {
        int i = base + j;
        if (i < NN) { g_off[i] = off; off += g_degi[i]; }
    }
}
__global__ void k_scatter(const int* __restrict__ src, const int* __restrict__ dst) {
    int e = blockIdx.x * blockDim.x + threadIdx.x;
    if (e >= NE) return;
    int d = dst[e];
    int p = g_off[d] + atomicAdd(&g_cnt[d], 1);
    g_ssrc[p] = src[e];
}
__global__ void k_dinv() {
    int i = blockIdx.x * blockDim.x + threadIdx.x;
    if (i < NN) g_deg[i] = rsqrtf(1.0f + (float)g_degi[i]);
}
__global__ void k_zero_stats() {
    int i = threadIdx.x;
    if (i < 2 * HID) g_stats[i] = 0.0f;
}

// ---------------- GEMM: g_s[m][n] = dinv[m] * sum_k X[m][k] * W[n][k] -------
template <int K>
__global__ void k_gemm(const float* __restrict__ X, const float* __restrict__ W) {
    __shared__ float As[32][33];
    __shared__ float Bs[32][132];

    const int t  = threadIdx.x;
    const int m0 = blockIdx.x * 32;
    const int ry = t >> 5;
    const int cx = t & 31;

    float acc[4][4] = {};

    for (int k0 = 0; k0 < K; k0 += 32) {
        {
            int r = t >> 5, kk = t & 31;
            #pragma unroll
            for (int i = 0; i < 4; i++) {
                int rr = r + i * 8;
                int m  = m0 + rr;
                As[rr][kk] = (m < NN) ? X[(size_t)m * K + k0 + kk] : 0.0f;
            }
        }
        {
            int kk = t & 31, n0 = t >> 5;
            #pragma unroll
            for (int i = 0; i < 16; i++) {
                int n = n0 + i * 8;
                Bs[kk][n] = W[(size_t)n * K + k0 + kk];
            }
        }
        __syncthreads();

        #pragma unroll
        for (int kk = 0; kk < 32; kk++) {
            float4 b = *(const float4*)&Bs[kk][cx * 4];
            #pragma unroll
            for (int i = 0; i < 4; i++) {
                float a = As[ry * 4 + i][kk];
                acc[i][0] += a * b.x;
                acc[i][1] += a * b.y;
                acc[i][2] += a * b.z;
                acc[i][3] += a * b.w;
            }
        }
        __syncthreads();
    }

    #pragma unroll
    for (int i = 0; i < 4; i++) {
        int m = m0 + ry * 4 + i;
        if (m < NN) {
            float d = g_deg[m];
            float4 v = make_float4(acc[i][0] * d, acc[i][1] * d,
                                   acc[i][2] * d, acc[i][3] * d);
            *(float4*)&g_s[(size_t)m * HID + cx * 4] = v;
        }
    }
}

// ---------------- CSR aggregation: one warp per node, no atomics ------------
__global__ void k_agg() {
    int gw   = (blockIdx.x * blockDim.x + threadIdx.x) >> 5;
    int lane = threadIdx.x & 31;
    if (gw >= NN) return;
    int beg = g_off[gw];
    int end = beg + g_degi[gw];
    size_t co = (size_t)lane * 4;
    float4 acc = *(const float4*)(g_s + (size_t)gw * HID + co);   // self-loop
    for (int e = beg; e < end; e++) {
        int u = g_ssrc[e];
        float4 v = *(const float4*)(g_s + (size_t)u * HID + co);
        acc.x += v.x; acc.y += v.y; acc.z += v.z; acc.w += v.w;
    }
    *(float4*)(g_acc + (size_t)gw * HID + co) = acc;
}

// ---------------- finish: v = acc*dinv + b, relu; column sum/sumsq ----------
__global__ void k_finish(const float* __restrict__ bias) {
    int c  = threadIdx.x;
    int r0 = blockIdx.x * 64;
    float bc = bias[c];
    float sum = 0.0f, sq = 0.0f;
    for (int i = 0; i < 64; i++) {
        int r = r0 + i;
        if (r >= NN) break;
        float v = g_acc[(size_t)r * HID + c] * g_deg[r] + bc;
        v = fmaxf(v, 0.0f);
        g_acc[(size_t)r * HID + c] = v;
        sum += v;
        sq  += v * v;
    }
    atomicAdd(&g_stats[c],       sum);
    atomicAdd(&g_stats[HID + c], sq);
}

// ---------------- batchnorm normalize -> emb[l] -----------------------------
__global__ void k_bn(const float* __restrict__ gamma, const float* __restrict__ beta,
                     float* __restrict__ emb) {
    int idx = blockIdx.x * blockDim.x + threadIdx.x;
    if (idx >= NN * HID) return;
    int   c    = idx & (HID - 1);
    float mean = g_stats[c] * (1.0f / NN);
    float var  = g_stats[HID + c] * (1.0f / NN) - mean * mean;
    float v    = (g_acc[idx] - mean) * rsqrtf(var + BN_EPS) * gamma[c] + beta[c];
    emb[idx] = v;
}

// ---------------- attention pooling + projection, 32 rows per block ---------
// smem layout (floats):
//   sW  [128k][132t]  transposed W        16896
//   sE  [3l][128k][36r] transposed embs   13824
//   sP  [128k][36r]   pooled (transposed)  4608
//   sOW [128k][66o]   transposed out_w     8448
//   e_s [3][32], al [3][32]                 192
#define SM_W   0
#define SM_E   (SM_W + 128*132)
#define SM_P   (SM_E + 3*128*36)
#define SM_OW  (SM_P + 128*36)
#define SM_ES  (SM_OW + 128*66)
#define SM_AL  (SM_ES + 96)
#define SM_FLOATS (SM_AL + 96)

__global__ void k_att(const int* __restrict__ dp, const int* __restrict__ tp,
                      const int* __restrict__ dn, const int* __restrict__ tn,
                      const float* __restrict__ WD, const float* __restrict__ WT,
                      const float* __restrict__ qD, const float* __restrict__ qT,
                      const float* __restrict__ ow, const float* __restrict__ ob,
                      float* __restrict__ out) {
    extern __shared__ float sm[];
    __shared__ int s_node[32];

    const int tid = threadIdx.x;           // 256
    const int blk = blockIdx.x;            // 512
    const int grp = blk >> 7;              // 128 blocks per group
    const int jb  = (blk & 127) * 32;      // row offset within group

    const int*   ids = (grp == 0) ? dp : (grp == 1) ? tp : (grp == 2) ? dn : tn;
    const float* W   = (grp & 1) ? WT : WD;
    const float* q   = (grp & 1) ? qT : qD;

    if (tid < 32) s_node[tid] = ids[jb + tid];
    if (tid < 96) sm[SM_ES + tid] = 0.0f;
    __syncthreads();

    // stage W transposed: sW[k][t] = W[t*128+k]  (coalesced global reads)
    #pragma unroll
    for (int i = 0; i < 64; i++) {
        int idx = i * 256 + tid;
        int t = idx >> 7, k = idx & 127;
        sm[SM_W + k * 132 + t] = W[idx];
    }
    // stage out_w transposed: sOW[k][o] = ow[o*128+k]
    #pragma unroll
    for (int i = 0; i < 32; i++) {
        int idx = i * 256 + tid;
        int o = idx >> 7, k = idx & 127;
        sm[SM_OW + k * 66 + o] = ow[idx];
    }
    // stage emb transposed: sE[l][k][r] = emb_l[node[r]][k]
    #pragma unroll
    for (int l = 0; l < 3; l++)
        #pragma unroll
        for (int i = 0; i < 16; i++) {
            int idx = i * 256 + tid;
            int r = idx >> 7, k = idx & 127;
            sm[SM_E + ((l * 128 + k) * 36) + r] = g_emb[l][(size_t)s_node[r] * HID + k];
        }
    __syncthreads();

    const int tr = tid & 7;     // r0 = tr*4
    const int tt = tid >> 3;    // t0 = tt*4
    const int r0 = tr * 4;
    const int t0 = tt * 4;

    float ql0 = q[t0], ql1 = q[t0 + 1], ql2 = q[t0 + 2], ql3 = q[t0 + 3];

    // e[l][r] = sum_t lrelu(dot(emb_l[r], W[t])) * q[t]
    for (int l = 0; l < 3; l++) {
        float acc[4][4];
        #pragma unroll
        for (int i = 0; i < 4; i++)
            #pragma unroll
            for (int j = 0; j < 4; j++) acc[i][j] = 0.0f;

        const float* eb = sm + SM_E + (l * 128) * 36;
        #pragma unroll 4
        for (int k = 0; k < 128; k++) {
            float4 a = *(const float4*)(eb + k * 36 + r0);
            float4 b = *(const float4*)(sm + SM_W + k * 132 + t0);
            acc[0][0] += a.x * b.x; acc[0][1] += a.x * b.y; acc[0][2] += a.x * b.z; acc[0][3] += a.x * b.w;
            acc[1][0] += a.y * b.x; acc[1][1] += a.y * b.y; acc[1][2] += a.y * b.z; acc[1][3] += a.y * b.w;
            acc[2][0] += a.z * b.x; acc[2][1] += a.z * b.y; acc[2][2] += a.z * b.z; acc[2][3] += a.z * b.w;
            acc[3][0] += a.w * b.x; acc[3][1] += a.w * b.y; acc[3][2] += a.w * b.z; acc[3][3] += a.w * b.w;
        }
        #pragma unroll
        for (int i = 0; i < 4; i++) {
            float h0 = acc[i][0], h1 = acc[i][1], h2 = acc[i][2], h3 = acc[i][3];
            h0 = (h0 > 0.0f) ? h0 : SLOPE * h0;
            h1 = (h1 > 0.0f) ? h1 : SLOPE * h1;
            h2 = (h2 > 0.0f) ? h2 : SLOPE * h2;
            h3 = (h3 > 0.0f) ? h3 : SLOPE * h3;
            float pe = h0 * ql0 + h1 * ql1 + h2 * ql2 + h3 * ql3;
            atomicAdd(&sm[SM_ES + l * 32 + r0 + i], pe);
        }
    }
    __syncthreads();

    // softmax over layers per row
    if (tid < 32) {
        float e0 = sm[SM_ES + tid], e1 = sm[SM_ES + 32 + tid], e2 = sm[SM_ES + 64 + tid];
        float m  = fmaxf(e0, fmaxf(e1, e2));
        float a0 = expf(e0 - m), a1 = expf(e1 - m), a2 = expf(e2 - m);
        float s  = 1.0f / (a0 + a1 + a2);
        sm[SM_AL + tid]      = a0 * s;
        sm[SM_AL + 32 + tid] = a1 * s;
        sm[SM_AL + 64 + tid] = a2 * s;
    }
    __syncthreads();

    // pooled (transposed): sP[k][r] = sum_l alpha[l][r] * sE[l][k][r]
    #pragma unroll
    for (int i = 0; i < 16; i++) {
        int idx = i * 256 + tid;
        int k = idx >> 5, r = idx & 31;
        float v = sm[SM_AL + r]      * sm[SM_E + (0 * 128 + k) * 36 + r]
                + sm[SM_AL + 32 + r] * sm[SM_E + (1 * 128 + k) * 36 + r]
                + sm[SM_AL + 64 + r] * sm[SM_E + (2 * 128 + k) * 36 + r];
        sm[SM_P + k * 36 + r] = v;
    }
    __syncthreads();

    // out projection: z[r][o] = pooled[r] . ow[o] + ob[o]
    {
        const int o0 = tt * 2;   // 32 tt-groups x 2 cols = 64
        float a0 = 0, a1 = 0, b0 = 0, b1 = 0, c0 = 0, c1 = 0, d0 = 0, d1 = 0;
        #pragma unroll 4
        for (int k = 0; k < 128; k++) {
            float4 p = *(const float4*)(sm + SM_P + k * 36 + r0);
            float2 w2 = *(const float2*)(sm + SM_OW + k * 66 + o0);
            a0 += p.x * w2.x; a1 += p.x * w2.y;
            b0 += p.y * w2.x; b1 += p.y * w2.y;
            c0 += p.z * w2.x; c1 += p.z * w2.y;
            d0 += p.w * w2.x; d1 += p.w * w2.y;
        }
        float ob0 = ob[o0], ob1 = ob[o0 + 1];
        int row = blk * 32 + r0;
        out[(size_t)(row + 0) * OUTD + o0]     = a0 + ob0;
        out[(size_t)(row + 0) * OUTD + o0 + 1] = a1 + ob1;
        out[(size_t)(row + 1) * OUTD + o0]     = b0 + ob0;
        out[(size_t)(row + 1) * OUTD + o0 + 1] = b1 + ob1;
        out[(size_t)(row + 2) * OUTD + o0]     = c0 + ob0;
        out[(size_t)(row + 2) * OUTD + o0 + 1] = c1 + ob1;
        out[(size_t)(row + 3) * OUTD + o0]     = d0 + ob0;
        out[(size_t)(row + 3) * OUTD + o0 + 1] = d1 + ob1;
    }
}

// ---------------- launch -----------------------------------------------------
extern "C" void kernel_launch(void* const* d_in, const int* in_sizes, int n_in,
                              void* d_out, int out_size) {
    const float* x     = (const float*)d_in[0];
    const int*   ei    = (const int*)  d_in[1];
    const int*   dp    = (const int*)  d_in[2];
    const int*   tp    = (const int*)  d_in[3];
    const int*   dn    = (const int*)  d_in[4];
    const int*   tn    = (const int*)  d_in[5];
    const float* w0    = (const float*)d_in[7];
    const float* b0    = (const float*)d_in[8];
    const float* w1    = (const float*)d_in[9];
    const float* b1    = (const float*)d_in[10];
    const float* w2    = (const float*)d_in[11];
    const float* b2    = (const float*)d_in[12];
    const float* gamma = (const float*)d_in[13];
    const float* beta  = (const float*)d_in[14];
    const float* WD    = (const float*)d_in[15];
    const float* WT    = (const float*)d_in[16];
    const float* qD    = (const float*)d_in[17];
    const float* qT    = (const float*)d_in[18];
    const float* ow    = (const float*)d_in[19];
    const float* ob    = (const float*)d_in[20];
    float*       out   = (float*)d_out;

    const int* src = ei;
    const int* dst = ei + NE;

    float* embBase = nullptr;
    cudaGetSymbolAddress((void**)&embBase, g_emb);

    static bool attr_done = false;
    if (!attr_done) {
        cudaFuncSetAttribute(k_att, cudaFuncAttributeMaxDynamicSharedMemorySize,
                             SM_FLOATS * (int)sizeof(float));
        attr_done = true;
    }

    // CSR build + dinv (every call; deterministic inputs)
    k_init     <<<(NN + 255) / 256, 256>>>();
    k_deg_count<<<(NE + 255) / 256, 256>>>(dst);
    k_scan     <<<1, 1024>>>();
    k_scatter  <<<(NE + 255) / 256, 256>>>(src, dst);
    k_dinv     <<<(NN + 255) / 256, 256>>>();

    const int GEMM_BLOCKS = (NN + 31) / 32;
    const int AGG_BLOCKS  = (NN * 32 + 255) / 256;

    const float* ws[3] = {w0, w1, w2};
    const float* bs[3] = {b0, b1, b2};

    for (int l = 0; l < 3; l++) {
        k_zero_stats<<<1, 256>>>();
        if (l == 0)
            k_gemm<IND><<<GEMM_BLOCKS, 256>>>(x, ws[0]);
        else
            k_gemm<HID><<<GEMM_BLOCKS, 256>>>(embBase + (size_t)(l - 1) * NN * HID, ws[l]);
        k_agg   <<<AGG_BLOCKS, 256>>>();
        k_finish<<<(NN + 63) / 64, 128>>>(bs[l]);
        k_bn    <<<(NN * HID + 255) / 256, 256>>>(gamma, beta,
                                                  embBase + (size_t)l * NN * HID);
    }

    k_att<<<512, 256, SM_FLOATS * (int)sizeof(float)>>>(dp, tp, dn, tn, WD, WT,
                                                        qD, qT, ow, ob, out);
}

// round 3
// speedup vs baseline: 6.7354x; 1.0870x over previous
#include <cuda_runtime.h>
#include <math.h>

#define NN   50000
#define NE   800000
#define IND  256
#define HID  128
#define OUTD 64
#define NB   4096
#define BN_EPS 1e-5f
#define SLOPE  0.01f

// ---------------- scratch (device globals; no allocation allowed) ----------
__device__ float g_deg [NN];                    // dinv
__device__ int   g_degi[NN];                    // int degree (no self loop)
__device__ int   g_off [NN];                    // CSR offsets
__device__ int   g_cnt [NN];                    // scatter counters
__device__ int   g_ssrc[NE];                    // src ids sorted by dst
__device__ float g_s   [(size_t)NN * HID];      // dinv-scaled linear output
__device__ float g_acc [(size_t)NN * HID];      // aggregation result / post-relu
__device__ float g_emb [3][(size_t)NN * HID];   // per-layer BN outputs
__device__ float g_stats[2 * HID];              // column sum / sumsq

// ---------------- f32x2 helpers ---------------------------------------------
__device__ __forceinline__ unsigned long long dup2(float x) {
    unsigned long long r;
    asm("mov.b64 %0, {%1, %1};" : "=l"(r) : "r"(__float_as_uint(x)));
    return r;
}
__device__ __forceinline__ void fma2(unsigned long long& d, unsigned long long a,
                                     unsigned long long b) {
    asm("fma.rn.f32x2 %0, %1, %2, %0;" : "+l"(d) : "l"(a), "l"(b));
}
__device__ __forceinline__ float lo32(unsigned long long v) {
    return __uint_as_float((unsigned)(v & 0xffffffffull));
}
__device__ __forceinline__ float hi32(unsigned long long v) {
    return __uint_as_float((unsigned)(v >> 32));
}

// ---------------- init / degree / dinv --------------------------------------
__global__ void k_init() {
    int i = blockIdx.x * blockDim.x + threadIdx.x;
    if (i < NN) { g_degi[i] = 0; g_cnt[i] = 0; }
}
__global__ void k_deg_count(const int* __restrict__ dst) {
    int e = blockIdx.x * blockDim.x + threadIdx.x;
    if (e < NE) atomicAdd(&g_degi[dst[e]], 1);
}
__global__ void k_scan() {                      // 1 block, 1024 threads
    const int PER = (NN + 1023) / 1024;         // 49
    int t = threadIdx.x;
    int base = t * PER;
    int sum = 0;
    for (int j = 0; j < PER; j++) { int i = base + j; if (i < NN) sum += g_degi[i]; }
    __shared__ int tmp[1024];
    tmp[t] = sum;
    __syncthreads();
    for (int d = 1; d < 1024; d <<= 1) {
        int v = (t >= d) ? tmp[t - d] : 0;
        __syncthreads();
        tmp[t] += v;
        __syncthreads();
    }
    int off = (t == 0) ? 0 : tmp[t - 1];
    for (int j = 0; j < PER; j++) {
        int i = base + j;
        if (i < NN) { g_off[i] = off; off += g_degi[i]; }
    }
}
__global__ void k_scatter(const int* __restrict__ src, const int* __restrict__ dst) {
    int e = blockIdx.x * blockDim.x + threadIdx.x;
    if (e >= NE) return;
    int d = dst[e];
    int p = g_off[d] + atomicAdd(&g_cnt[d], 1);
    g_ssrc[p] = src[e];
}
__global__ void k_dinv() {
    int i = blockIdx.x * blockDim.x + threadIdx.x;
    if (i < NN) g_deg[i] = rsqrtf(1.0f + (float)g_degi[i]);
}
__global__ void k_zero_stats() {
    int i = threadIdx.x;
    if (i < 2 * HID) g_stats[i] = 0.0f;
}

// ---------------- GEMM (f32x2): g_s[m][n] = dinv[m]*sum_k X[m][k]*W[n][k] ---
// 128x128 block tile, 256 threads, 8x8 per thread, packed-pair accumulators.
template <int K>
__global__ void __launch_bounds__(256, 2)
k_gemm(const float* __restrict__ X, const float* __restrict__ W) {
    __shared__ float As[16][132];   // [kk][m]
    __shared__ float Bs[16][132];   // [kk][n]

    const int t  = threadIdx.x;
    const int m0 = blockIdx.x * 128;
    const int tm = (t >> 4) * 8;    // row base within tile
    const int tn = (t & 15) * 8;    // col base within tile

    unsigned long long acc[4][8];   // [m-pair][n]
    #pragma unroll
    for (int p = 0; p < 4; p++)
        #pragma unroll
        for (int j = 0; j < 8; j++) acc[p][j] = 0ull;

    for (int k0 = 0; k0 < K; k0 += 16) {
        // stage A transposed: As[kk][m]
        #pragma unroll
        for (int i = 0; i < 2; i++) {
            int fid = i * 256 + t;          // 0..511
            int r   = fid >> 2;
            int c4  = (fid & 3) * 4;
            int m   = m0 + r;
            float4 v = (m < NN) ? *(const float4*)(X + (size_t)m * K + k0 + c4)
                                : make_float4(0.f, 0.f, 0.f, 0.f);
            As[c4 + 0][r] = v.x;
            As[c4 + 1][r] = v.y;
            As[c4 + 2][r] = v.z;
            As[c4 + 3][r] = v.w;
        }
        // stage B transposed: Bs[kk][n]
        #pragma unroll
        for (int i = 0; i < 2; i++) {
            int fid = i * 256 + t;
            int n   = fid >> 2;
            int c4  = (fid & 3) * 4;
            float4 v = *(const float4*)(W + (size_t)n * K + k0 + c4);
            Bs[c4 + 0][n] = v.x;
            Bs[c4 + 1][n] = v.y;
            Bs[c4 + 2][n] = v.z;
            Bs[c4 + 3][n] = v.w;
        }
        __syncthreads();

        #pragma unroll
        for (int kk = 0; kk < 16; kk++) {
            ulonglong2 aP0 = *(const ulonglong2*)&As[kk][tm];       // pairs (tm,tm+1),(tm+2,tm+3)
            ulonglong2 aP1 = *(const ulonglong2*)&As[kk][tm + 4];   // pairs (tm+4..),(tm+6..)
            float4 b0 = *(const float4*)&Bs[kk][tn];
            float4 b1 = *(const float4*)&Bs[kk][tn + 4];
            unsigned long long bd[8];
            bd[0] = dup2(b0.x); bd[1] = dup2(b0.y); bd[2] = dup2(b0.z); bd[3] = dup2(b0.w);
            bd[4] = dup2(b1.x); bd[5] = dup2(b1.y); bd[6] = dup2(b1.z); bd[7] = dup2(b1.w);
            #pragma unroll
            for (int j = 0; j < 8; j++) {
                fma2(acc[0][j], aP0.x, bd[j]);
                fma2(acc[1][j], aP0.y, bd[j]);
                fma2(acc[2][j], aP1.x, bd[j]);
                fma2(acc[3][j], aP1.y, bd[j]);
            }
        }
        __syncthreads();
    }

    // epilogue: scale by dinv and store two rows per pair
    #pragma unroll
    for (int p = 0; p < 4; p++) {
        int r0 = m0 + tm + 2 * p;
        if (r0 < NN) {
            float d = g_deg[r0];
            float4 v0 = make_float4(lo32(acc[p][0]) * d, lo32(acc[p][1]) * d,
                                    lo32(acc[p][2]) * d, lo32(acc[p][3]) * d);
            float4 v1 = make_float4(lo32(acc[p][4]) * d, lo32(acc[p][5]) * d,
                                    lo32(acc[p][6]) * d, lo32(acc[p][7]) * d);
            *(float4*)&g_s[(size_t)r0 * HID + tn]     = v0;
            *(float4*)&g_s[(size_t)r0 * HID + tn + 4] = v1;
        }
        int r1 = r0 + 1;
        if (r1 < NN) {
            float d = g_deg[r1];
            float4 v0 = make_float4(hi32(acc[p][0]) * d, hi32(acc[p][1]) * d,
                                    hi32(acc[p][2]) * d, hi32(acc[p][3]) * d);
            float4 v1 = make_float4(hi32(acc[p][4]) * d, hi32(acc[p][5]) * d,
                                    hi32(acc[p][6]) * d, hi32(acc[p][7]) * d);
            *(float4*)&g_s[(size_t)r1 * HID + tn]     = v0;
            *(float4*)&g_s[(size_t)r1 * HID + tn + 4] = v1;
        }
    }
}

// ---------------- CSR aggregation: one warp per node, no atomics ------------
__global__ void k_agg() {
    int gw   = (blockIdx.x * blockDim.x + threadIdx.x) >> 5;
    int lane = threadIdx.x & 31;
    if (gw >= NN) return;
    int beg = g_off[gw];
    int end = beg + g_degi[gw];
    const float4* S = (const float4*)g_s;          // node*32 + lane
    float4 acc = S[(size_t)gw * 32 + lane];        // self-loop
    int e = beg;
    for (; e + 4 <= end; e += 4) {
        int u0 = g_ssrc[e], u1 = g_ssrc[e + 1], u2 = g_ssrc[e + 2], u3 = g_ssrc[e + 3];
        float4 v0 = S[(size_t)u0 * 32 + lane];
        float4 v1 = S[(size_t)u1 * 32 + lane];
        float4 v2 = S[(size_t)u2 * 32 + lane];
        float4 v3 = S[(size_t)u3 * 32 + lane];
        acc.x += (v0.x + v1.x) + (v2.x + v3.x);
        acc.y += (v0.y + v1.y) + (v2.y + v3.y);
        acc.z += (v0.z + v1.z) + (v2.z + v3.z);
        acc.w += (v0.w + v1.w) + (v2.w + v3.w);
    }
    for (; e < end; e++) {
        int u = g_ssrc[e];
        float4 v = S[(size_t)u * 32 + lane];
        acc.x += v.x; acc.y += v.y; acc.z += v.z; acc.w += v.w;
    }
    ((float4*)g_acc)[(size_t)gw * 32 + lane] = acc;
}

// ---------------- finish: v = acc*dinv + b, relu; column sum/sumsq ----------
__global__ void k_finish(const float* __restrict__ bias) {
    int c  = threadIdx.x;
    int r0 = blockIdx.x * 64;
    float bc = bias[c];
    float sum = 0.0f, sq = 0.0f;
    for (int i = 0; i < 64; i++) {
        int r = r0 + i;
        if (r >= NN) break;
        float v = g_acc[(size_t)r * HID + c] * g_deg[r] + bc;
        v = fmaxf(v, 0.0f);
        g_acc[(size_t)r * HID + c] = v;
        sum += v;
        sq  += v * v;
    }
    atomicAdd(&g_stats[c],       sum);
    atomicAdd(&g_stats[HID + c], sq);
}

// ---------------- batchnorm normalize -> emb[l] -----------------------------
__global__ void k_bn(const float* __restrict__ gamma, const float* __restrict__ beta,
                     float* __restrict__ emb) {
    int idx = blockIdx.x * blockDim.x + threadIdx.x;
    if (idx >= NN * HID) return;
    int   c    = idx & (HID - 1);
    float mean = g_stats[c] * (1.0f / NN);
    float var  = g_stats[HID + c] * (1.0f / NN) - mean * mean;
    float v    = (g_acc[idx] - mean) * rsqrtf(var + BN_EPS) * gamma[c] + beta[c];
    emb[idx] = v;
}

// ---------------- attention pooling + projection, 32 rows per block ---------
#define SM_W   0
#define SM_E   (SM_W + 128*132)
#define SM_P   (SM_E + 3*128*36)
#define SM_OW  (SM_P + 128*36)
#define SM_ES  (SM_OW + 128*66)
#define SM_AL  (SM_ES + 96)
#define SM_FLOATS (SM_AL + 96)

__global__ void k_att(const int* __restrict__ dp, const int* __restrict__ tp,
                      const int* __restrict__ dn, const int* __restrict__ tn,
                      const float* __restrict__ WD, const float* __restrict__ WT,
                      const float* __restrict__ qD, const float* __restrict__ qT,
                      const float* __restrict__ ow, const float* __restrict__ ob,
                      float* __restrict__ out) {
    extern __shared__ float sm[];
    __shared__ int s_node[32];

    const int tid = threadIdx.x;           // 256
    const int blk = blockIdx.x;            // 512
    const int grp = blk >> 7;
    const int jb  = (blk & 127) * 32;

    const int*   ids = (grp == 0) ? dp : (grp == 1) ? tp : (grp == 2) ? dn : tn;
    const float* W   = (grp & 1) ? WT : WD;
    const float* q   = (grp & 1) ? qT : qD;

    if (tid < 32) s_node[tid] = ids[jb + tid];
    if (tid < 96) sm[SM_ES + tid] = 0.0f;
    __syncthreads();

    #pragma unroll
    for (int i = 0; i < 64; i++) {
        int idx = i * 256 + tid;
        int t = idx >> 7, k = idx & 127;
        sm[SM_W + k * 132 + t] = W[idx];
    }
    #pragma unroll
    for (int i = 0; i < 32; i++) {
        int idx = i * 256 + tid;
        int o = idx >> 7, k = idx & 127;
        sm[SM_OW + k * 66 + o] = ow[idx];
    }
    #pragma unroll
    for (int l = 0; l < 3; l++)
        #pragma unroll
        for (int i = 0; i < 16; i++) {
            int idx = i * 256 + tid;
            int r = idx >> 7, k = idx & 127;
            sm[SM_E + ((l * 128 + k) * 36) + r] = g_emb[l][(size_t)s_node[r] * HID + k];
        }
    __syncthreads();

    const int tr = tid & 7;
    const int tt = tid >> 3;
    const int r0 = tr * 4;
    const int t0 = tt * 4;

    float ql0 = q[t0], ql1 = q[t0 + 1], ql2 = q[t0 + 2], ql3 = q[t0 + 3];

    for (int l = 0; l < 3; l++) {
        float acc[4][4];
        #pragma unroll
        for (int i = 0; i < 4; i++)
            #pragma unroll
            for (int j = 0; j < 4; j++) acc[i][j] = 0.0f;

        const float* eb = sm + SM_E + (l * 128) * 36;
        #pragma unroll 4
        for (int k = 0; k < 128; k++) {
            float4 a = *(const float4*)(eb + k * 36 + r0);
            float4 b = *(const float4*)(sm + SM_W + k * 132 + t0);
            acc[0][0] += a.x * b.x; acc[0][1] += a.x * b.y; acc[0][2] += a.x * b.z; acc[0][3] += a.x * b.w;
            acc[1][0] += a.y * b.x; acc[1][1] += a.y * b.y; acc[1][2] += a.y * b.z; acc[1][3] += a.y * b.w;
            acc[2][0] += a.z * b.x; acc[2][1] += a.z * b.y; acc[2][2] += a.z * b.z; acc[2][3] += a.z * b.w;
            acc[3][0] += a.w * b.x; acc[3][1] += a.w * b.y; acc[3][2] += a.w * b.z; acc[3][3] += a.w * b.w;
        }
        #pragma unroll
        for (int i = 0; i < 4; i++) {
            float h0 = acc[i][0], h1 = acc[i][1], h2 = acc[i][2], h3 = acc[i][3];
            h0 = (h0 > 0.0f) ? h0 : SLOPE * h0;
            h1 = (h1 > 0.0f) ? h1 : SLOPE * h1;
            h2 = (h2 > 0.0f) ? h2 : SLOPE * h2;
            h3 = (h3 > 0.0f) ? h3 : SLOPE * h3;
            float pe = h0 * ql0 + h1 * ql1 + h2 * ql2 + h3 * ql3;
            atomicAdd(&sm[SM_ES + l * 32 + r0 + i], pe);
        }
    }
    __syncthreads();

    if (tid < 32) {
        float e0 = sm[SM_ES + tid], e1 = sm[SM_ES + 32 + tid], e2 = sm[SM_ES + 64 + tid];
        float m  = fmaxf(e0, fmaxf(e1, e2));
        float a0 = expf(e0 - m), a1 = expf(e1 - m), a2 = expf(e2 - m);
        float s  = 1.0f / (a0 + a1 + a2);
        sm[SM_AL + tid]      = a0 * s;
        sm[SM_AL + 32 + tid] = a1 * s;
        sm[SM_AL + 64 + tid] = a2 * s;
    }
    __syncthreads();

    #pragma unroll
    for (int i = 0; i < 16; i++) {
        int idx = i * 256 + tid;
        int k = idx >> 5, r = idx & 31;
        float v = sm[SM_AL + r]      * sm[SM_E + (0 * 128 + k) * 36 + r]
                + sm[SM_AL + 32 + r] * sm[SM_E + (1 * 128 + k) * 36 + r]
                + sm[SM_AL + 64 + r] * sm[SM_E + (2 * 128 + k) * 36 + r];
        sm[SM_P + k * 36 + r] = v;
    }
    __syncthreads();

    {
        const int o0 = tt * 2;
        float a0 = 0, a1 = 0, b0 = 0, b1 = 0, c0 = 0, c1 = 0, d0 = 0, d1 = 0;
        #pragma unroll 4
        for (int k = 0; k < 128; k++) {
            float4 p = *(const float4*)(sm + SM_P + k * 36 + r0);
            float2 w2 = *(const float2*)(sm + SM_OW + k * 66 + o0);
            a0 += p.x * w2.x; a1 += p.x * w2.y;
            b0 += p.y * w2.x; b1 += p.y * w2.y;
            c0 += p.z * w2.x; c1 += p.z * w2.y;
            d0 += p.w * w2.x; d1 += p.w * w2.y;
        }
        float ob0 = ob[o0], ob1 = ob[o0 + 1];
        int row = blk * 32 + r0;
        out[(size_t)(row + 0) * OUTD + o0]     = a0 + ob0;
        out[(size_t)(row + 0) * OUTD + o0 + 1] = a1 + ob1;
        out[(size_t)(row + 1) * OUTD + o0]     = b0 + ob0;
        out[(size_t)(row + 1) * OUTD + o0 + 1] = b1 + ob1;
        out[(size_t)(row + 2) * OUTD + o0]     = c0 + ob0;
        out[(size_t)(row + 2) * OUTD + o0 + 1] = c1 + ob1;
        out[(size_t)(row + 3) * OUTD + o0]     = d0 + ob0;
        out[(size_t)(row + 3) * OUTD + o0 + 1] = d1 + ob1;
    }
}

// ---------------- launch -----------------------------------------------------
extern "C" void kernel_launch(void* const* d_in, const int* in_sizes, int n_in,
                              void* d_out, int out_size) {
    const float* x     = (const float*)d_in[0];
    const int*   ei    = (const int*)  d_in[1];
    const int*   dp    = (const int*)  d_in[2];
    const int*   tp    = (const int*)  d_in[3];
    const int*   dn    = (const int*)  d_in[4];
    const int*   tn    = (const int*)  d_in[5];
    const float* w0    = (const float*)d_in[7];
    const float* b0    = (const float*)d_in[8];
    const float* w1    = (const float*)d_in[9];
    const float* b1    = (const float*)d_in[10];
    const float* w2    = (const float*)d_in[11];
    const float* b2    = (const float*)d_in[12];
    const float* gamma = (const float*)d_in[13];
    const float* beta  = (const float*)d_in[14];
    const float* WD    = (const float*)d_in[15];
    const float* WT    = (const float*)d_in[16];
    const float* qD    = (const float*)d_in[17];
    const float* qT    = (const float*)d_in[18];
    const float* ow    = (const float*)d_in[19];
    const float* ob    = (const float*)d_in[20];
    float*       out   = (float*)d_out;

    const int* src = ei;
    const int* dst = ei + NE;

    float* embBase = nullptr;
    cudaGetSymbolAddress((void**)&embBase, g_emb);

    static bool attr_done = false;
    if (!attr_done) {
        cudaFuncSetAttribute(k_att, cudaFuncAttributeMaxDynamicSharedMemorySize,
                             SM_FLOATS * (int)sizeof(float));
        attr_done = true;
    }

    k_init     <<<(NN + 255) / 256, 256>>>();
    k_deg_count<<<(NE + 255) / 256, 256>>>(dst);
    k_scan     <<<1, 1024>>>();
    k_scatter  <<<(NE + 255) / 256, 256>>>(src, dst);
    k_dinv     <<<(NN + 255) / 256, 256>>>();

    const int GEMM_BLOCKS = (NN + 127) / 128;        // 391
    const int AGG_BLOCKS  = (NN * 32 + 255) / 256;

    const float* ws[3] = {w0, w1, w2};
    const float* bs[3] = {b0, b1, b2};

    for (int l = 0; l < 3; l++) {
        k_zero_stats<<<1, 256>>>();
        if (l == 0)
            k_gemm<IND><<<GEMM_BLOCKS, 256>>>(x, ws[0]);
        else
            k_gemm<HID><<<GEMM_BLOCKS, 256>>>(embBase + (size_t)(l - 1) * NN * HID, ws[l]);
        k_agg   <<<AGG_BLOCKS, 256>>>();
        k_finish<<<(NN + 63) / 64, 128>>>(bs[l]);
        k_bn    <<<(NN * HID + 255) / 256, 256>>>(gamma, beta,
                                                  embBase + (size_t)l * NN * HID);
    }

    k_att<<<512, 256, SM_FLOATS * (int)sizeof(float)>>>(dp, tp, dn, tn, WD, WT,
                                                        qD, qT, ow, ob, out);
}

// round 4
// speedup vs baseline: 7.2445x; 1.0756x over previous
#include <cuda_runtime.h>
#include <math.h>

#define NN   50000
#define NE   800000
#define IND  256
#define HID  128
#define OUTD 64
#define NB   4096
#define BN_EPS 1e-5f
#define SLOPE  0.01f

// ---------------- scratch (device globals; no allocation allowed) ----------
__device__ int   g_degi[NN];                      // int degree (no self loop)
__device__ int   g_off [NN];                      // CSR offsets
__device__ int   g_cnt [NN];                      // scatter counters
__device__ int   g_ssrc[NE];                      // src ids sorted by dst
__device__ float g_s   [(size_t)NN * HID];        // dinv-scaled linear output
__device__ float g_accL[3][(size_t)NN * HID];     // per-layer pre-BN activations
__device__ float g_stats[3][2 * HID];             // per-layer column sum / sumsq

// ---------------- f32x2 helpers ---------------------------------------------
__device__ __forceinline__ unsigned long long dup2(float x) {
    unsigned long long r;
    asm("mov.b64 %0, {%1, %1};" : "=l"(r) : "r"(__float_as_uint(x)));
    return r;
}
__device__ __forceinline__ void fma2(unsigned long long& d, unsigned long long a,
                                     unsigned long long b) {
    asm("fma.rn.f32x2 %0, %1, %2, %0;" : "+l"(d) : "l"(a), "l"(b));
}
__device__ __forceinline__ float lo32(unsigned long long v) {
    return __uint_as_float((unsigned)(v & 0xffffffffull));
}
__device__ __forceinline__ float hi32(unsigned long long v) {
    return __uint_as_float((unsigned)(v >> 32));
}

// ---------------- init / degree / CSR ----------------------------------------
__global__ void k_init() {
    int i = blockIdx.x * blockDim.x + threadIdx.x;
    if (i < NN) { g_degi[i] = 0; g_cnt[i] = 0; }
    if (i < 3 * 2 * HID) ((float*)g_stats)[i] = 0.0f;
}
__global__ void k_deg_count(const int* __restrict__ dst) {
    int e = blockIdx.x * blockDim.x + threadIdx.x;
    if (e < NE) atomicAdd(&g_degi[dst[e]], 1);
}
__global__ void k_scan() {                      // 1 block, 1024 threads
    const int PER = (NN + 1023) / 1024;         // 49
    int t = threadIdx.x;
    int base = t * PER;
    int sum = 0;
    for (int j = 0; j < PER; j++) { int i = base + j; if (i < NN) sum += g_degi[i]; }
    __shared__ int tmp[1024];
    tmp[t] = sum;
    __syncthreads();
    for (int d = 1; d < 1024; d <<= 1) {
        int v = (t >= d) ? tmp[t - d] : 0;
        __syncthreads();
        tmp[t] += v;
        __syncthreads();
    }
    int off = (t == 0) ? 0 : tmp[t - 1];
    for (int j = 0; j < PER; j++) {
        int i = base + j;
        if (i < NN) { g_off[i] = off; off += g_degi[i]; }
    }
}
__global__ void k_scatter(const int* __restrict__ src, const int* __restrict__ dst) {
    int e = blockIdx.x * blockDim.x + threadIdx.x;
    if (e >= NE) return;
    int d = dst[e];
    int p = g_off[d] + atomicAdd(&g_cnt[d], 1);
    g_ssrc[p] = src[e];
}

// ---------------- GEMM (f32x2): g_s[m][n] = dinv[m]*sum_k A[m][k]*W[n][k] ---
// A = X (layer 0) or BN(g_accL[l-1]) applied on the fly during staging.
template <int K, bool BN>
__global__ void __launch_bounds__(256, 2)
k_gemm(const float* __restrict__ X, const float* __restrict__ W,
       const float* __restrict__ stats, const float* __restrict__ gamma,
       const float* __restrict__ beta) {
    __shared__ float As[16][132];   // [kk][m]
    __shared__ float Bs[16][132];   // [kk][n]
    __shared__ float sScale[HID], sShift[HID];

    const int t  = threadIdx.x;
    const int m0 = blockIdx.x * 128;
    const int tm = (t >> 4) * 8;
    const int tn = (t & 15) * 8;

    if (BN && t < HID) {
        float mean = stats[t] * (1.0f / NN);
        float var  = stats[HID + t] * (1.0f / NN) - mean * mean;
        float sc   = gamma[t] * rsqrtf(var + BN_EPS);
        sScale[t] = sc;
        sShift[t] = beta[t] - mean * sc;
    }
    if (BN) __syncthreads();

    unsigned long long acc[4][8];
    #pragma unroll
    for (int p = 0; p < 4; p++)
        #pragma unroll
        for (int j = 0; j < 8; j++) acc[p][j] = 0ull;

    for (int k0 = 0; k0 < K; k0 += 16) {
        #pragma unroll
        for (int i = 0; i < 2; i++) {
            int fid = i * 256 + t;          // 0..511
            int r   = fid >> 2;
            int c4  = (fid & 3) * 4;
            int m   = m0 + r;
            float4 v = (m < NN) ? *(const float4*)(X + (size_t)m * K + k0 + c4)
                                : make_float4(0.f, 0.f, 0.f, 0.f);
            if (BN) {
                v.x = v.x * sScale[k0 + c4 + 0] + sShift[k0 + c4 + 0];
                v.y = v.y * sScale[k0 + c4 + 1] + sShift[k0 + c4 + 1];
                v.z = v.z * sScale[k0 + c4 + 2] + sShift[k0 + c4 + 2];
                v.w = v.w * sScale[k0 + c4 + 3] + sShift[k0 + c4 + 3];
            }
            As[c4 + 0][r] = v.x;
            As[c4 + 1][r] = v.y;
            As[c4 + 2][r] = v.z;
            As[c4 + 3][r] = v.w;
        }
        #pragma unroll
        for (int i = 0; i < 2; i++) {
            int fid = i * 256 + t;
            int n   = fid >> 2;
            int c4  = (fid & 3) * 4;
            float4 v = *(const float4*)(W + (size_t)n * K + k0 + c4);
            Bs[c4 + 0][n] = v.x;
            Bs[c4 + 1][n] = v.y;
            Bs[c4 + 2][n] = v.z;
            Bs[c4 + 3][n] = v.w;
        }
        __syncthreads();

        #pragma unroll
        for (int kk = 0; kk < 16; kk++) {
            ulonglong2 aP0 = *(const ulonglong2*)&As[kk][tm];
            ulonglong2 aP1 = *(const ulonglong2*)&As[kk][tm + 4];
            float4 b0 = *(const float4*)&Bs[kk][tn];
            float4 b1 = *(const float4*)&Bs[kk][tn + 4];
            unsigned long long bd[8];
            bd[0] = dup2(b0.x); bd[1] = dup2(b0.y); bd[2] = dup2(b0.z); bd[3] = dup2(b0.w);
            bd[4] = dup2(b1.x); bd[5] = dup2(b1.y); bd[6] = dup2(b1.z); bd[7] = dup2(b1.w);
            #pragma unroll
            for (int j = 0; j < 8; j++) {
                fma2(acc[0][j], aP0.x, bd[j]);
                fma2(acc[1][j], aP0.y, bd[j]);
                fma2(acc[2][j], aP1.x, bd[j]);
                fma2(acc[3][j], aP1.y, bd[j]);
            }
        }
        __syncthreads();
    }

    #pragma unroll
    for (int p = 0; p < 4; p++) {
        int r0 = m0 + tm + 2 * p;
        if (r0 < NN) {
            float d = rsqrtf(1.0f + (float)g_degi[r0]);
            float4 v0 = make_float4(lo32(acc[p][0]) * d, lo32(acc[p][1]) * d,
                                    lo32(acc[p][2]) * d, lo32(acc[p][3]) * d);
            float4 v1 = make_float4(lo32(acc[p][4]) * d, lo32(acc[p][5]) * d,
                                    lo32(acc[p][6]) * d, lo32(acc[p][7]) * d);
            *(float4*)&g_s[(size_t)r0 * HID + tn]     = v0;
            *(float4*)&g_s[(size_t)r0 * HID + tn + 4] = v1;
        }
        int r1 = r0 + 1;
        if (r1 < NN) {
            float d = rsqrtf(1.0f + (float)g_degi[r1]);
            float4 v0 = make_float4(hi32(acc[p][0]) * d, hi32(acc[p][1]) * d,
                                    hi32(acc[p][2]) * d, hi32(acc[p][3]) * d);
            float4 v1 = make_float4(hi32(acc[p][4]) * d, hi32(acc[p][5]) * d,
                                    hi32(acc[p][6]) * d, hi32(acc[p][7]) * d);
            *(float4*)&g_s[(size_t)r1 * HID + tn]     = v0;
            *(float4*)&g_s[(size_t)r1 * HID + tn + 4] = v1;
        }
    }
}

// ---------------- fused CSR aggregation + bias/ReLU + stats ------------------
// One warp per node (8 nodes / 256-thread block; 50000 % 8 == 0).
__global__ void __launch_bounds__(256)
k_agg(const float* __restrict__ bias, float* __restrict__ outv,
      float* __restrict__ stats) {
    __shared__ float sSum[HID], sSq[HID];
    int t = threadIdx.x;
    if (t < HID) { sSum[t] = 0.0f; sSq[t] = 0.0f; }
    __syncthreads();

    int gw   = (blockIdx.x * 256 + t) >> 5;        // node id
    int lane = t & 31;
    int beg = g_off[gw];
    int end = beg + g_degi[gw];
    const float4* S = (const float4*)g_s;
    float4 acc = S[(size_t)gw * 32 + lane];        // self-loop
    int e = beg;
    for (; e + 4 <= end; e += 4) {
        int u0 = g_ssrc[e], u1 = g_ssrc[e + 1], u2 = g_ssrc[e + 2], u3 = g_ssrc[e + 3];
        float4 v0 = S[(size_t)u0 * 32 + lane];
        float4 v1 = S[(size_t)u1 * 32 + lane];
        float4 v2 = S[(size_t)u2 * 32 + lane];
        float4 v3 = S[(size_t)u3 * 32 + lane];
        acc.x += (v0.x + v1.x) + (v2.x + v3.x);
        acc.y += (v0.y + v1.y) + (v2.y + v3.y);
        acc.z += (v0.z + v1.z) + (v2.z + v3.z);
        acc.w += (v0.w + v1.w) + (v2.w + v3.w);
    }
    for (; e < end; e++) {
        int u = g_ssrc[e];
        float4 v = S[(size_t)u * 32 + lane];
        acc.x += v.x; acc.y += v.y; acc.z += v.z; acc.w += v.w;
    }

    float dinv = rsqrtf(1.0f + (float)g_degi[gw]);
    float4 b4 = ((const float4*)bias)[lane];
    float4 v;
    v.x = fmaxf(acc.x * dinv + b4.x, 0.0f);
    v.y = fmaxf(acc.y * dinv + b4.y, 0.0f);
    v.z = fmaxf(acc.z * dinv + b4.z, 0.0f);
    v.w = fmaxf(acc.w * dinv + b4.w, 0.0f);
    ((float4*)outv)[(size_t)gw * 32 + lane] = v;

    int c = lane * 4;
    atomicAdd(&sSum[c + 0], v.x);     atomicAdd(&sSq[c + 0], v.x * v.x);
    atomicAdd(&sSum[c + 1], v.y);     atomicAdd(&sSq[c + 1], v.y * v.y);
    atomicAdd(&sSum[c + 2], v.z);     atomicAdd(&sSq[c + 2], v.z * v.z);
    atomicAdd(&sSum[c + 3], v.w);     atomicAdd(&sSq[c + 3], v.w * v.w);
    __syncthreads();

    if (t < 32) {
        float4 s = *(const float4*)&sSum[t * 4];
        atomicAdd((float4*)&stats[t * 4], s);
    } else if (t < 64) {
        int j = t - 32;
        float4 s = *(const float4*)&sSq[j * 4];
        atomicAdd((float4*)&stats[HID + j * 4], s);
    }
}

// ---------------- attention pooling + projection, 32 rows per block ---------
#define SM_W   0
#define SM_E   (SM_W + 128*132)
#define SM_P   (SM_E + 3*128*36)
#define SM_OW  (SM_P + 128*36)
#define SM_ES  (SM_OW + 128*66)
#define SM_AL  (SM_ES + 96)
#define SM_SC  (SM_AL + 96)
#define SM_SH  (SM_SC + 3*128)
#define SM_FLOATS (SM_SH + 3*128)

__global__ void k_att(const int* __restrict__ dp, const int* __restrict__ tp,
                      const int* __restrict__ dn, const int* __restrict__ tn,
                      const float* __restrict__ WD, const float* __restrict__ WT,
                      const float* __restrict__ qD, const float* __restrict__ qT,
                      const float* __restrict__ ow, const float* __restrict__ ob,
                      const float* __restrict__ gamma, const float* __restrict__ beta,
                      float* __restrict__ out) {
    extern __shared__ float sm[];
    __shared__ int s_node[32];

    const int tid = threadIdx.x;           // 256
    const int blk = blockIdx.x;            // 512
    const int grp = blk >> 7;
    const int jb  = (blk & 127) * 32;

    const int*   ids = (grp == 0) ? dp : (grp == 1) ? tp : (grp == 2) ? dn : tn;
    const float* W   = (grp & 1) ? WT : WD;
    const float* q   = (grp & 1) ? qT : qD;

    if (tid < 32) s_node[tid] = ids[jb + tid];
    if (tid < 96) sm[SM_ES + tid] = 0.0f;
    if (tid < 128) {
        #pragma unroll
        for (int l = 0; l < 3; l++) {
            const float* st = g_stats[l];
            float mean = st[tid] * (1.0f / NN);
            float var  = st[HID + tid] * (1.0f / NN) - mean * mean;
            float sc   = gamma[tid] * rsqrtf(var + BN_EPS);
            sm[SM_SC + l * 128 + tid] = sc;
            sm[SM_SH + l * 128 + tid] = beta[tid] - mean * sc;
        }
    }
    __syncthreads();

    #pragma unroll
    for (int i = 0; i < 64; i++) {
        int idx = i * 256 + tid;
        int t = idx >> 7, k = idx & 127;
        sm[SM_W + k * 132 + t] = W[idx];
    }
    #pragma unroll
    for (int i = 0; i < 32; i++) {
        int idx = i * 256 + tid;
        int o = idx >> 7, k = idx & 127;
        sm[SM_OW + k * 66 + o] = ow[idx];
    }
    #pragma unroll
    for (int l = 0; l < 3; l++)
        #pragma unroll
        for (int i = 0; i < 16; i++) {
            int idx = i * 256 + tid;
            int r = idx >> 7, k = idx & 127;
            float raw = g_accL[l][(size_t)s_node[r] * HID + k];
            sm[SM_E + ((l * 128 + k) * 36) + r] =
                raw * sm[SM_SC + l * 128 + k] + sm[SM_SH + l * 128 + k];
        }
    __syncthreads();

    const int tr = tid & 7;
    const int tt = tid >> 3;
    const int r0 = tr * 4;
    const int t0 = tt * 4;

    float ql0 = q[t0], ql1 = q[t0 + 1], ql2 = q[t0 + 2], ql3 = q[t0 + 3];

    for (int l = 0; l < 3; l++) {
        float acc[4][4];
        #pragma unroll
        for (int i = 0; i < 4; i++)
            #pragma unroll
            for (int j = 0; j < 4; j++) acc[i][j] = 0.0f;

        const float* eb = sm + SM_E + (l * 128) * 36;
        #pragma unroll 4
        for (int k = 0; k < 128; k++) {
            float4 a = *(const float4*)(eb + k * 36 + r0);
            float4 b = *(const float4*)(sm + SM_W + k * 132 + t0);
            acc[0][0] += a.x * b.x; acc[0][1] += a.x * b.y; acc[0][2] += a.x * b.z; acc[0][3] += a.x * b.w;
            acc[1][0] += a.y * b.x; acc[1][1] += a.y * b.y; acc[1][2] += a.y * b.z; acc[1][3] += a.y * b.w;
            acc[2][0] += a.z * b.x; acc[2][1] += a.z * b.y; acc[2][2] += a.z * b.z; acc[2][3] += a.z * b.w;
            acc[3][0] += a.w * b.x; acc[3][1] += a.w * b.y; acc[3][2] += a.w * b.z; acc[3][3] += a.w * b.w;
        }
        #pragma unroll
        for (int i = 0; i < 4; i++) {
            float h0 = acc[i][0], h1 = acc[i][1], h2 = acc[i][2], h3 = acc[i][3];
            h0 = (h0 > 0.0f) ? h0 : SLOPE * h0;
            h1 = (h1 > 0.0f) ? h1 : SLOPE * h1;
            h2 = (h2 > 0.0f) ? h2 : SLOPE * h2;
            h3 = (h3 > 0.0f) ? h3 : SLOPE * h3;
            float pe = h0 * ql0 + h1 * ql1 + h2 * ql2 + h3 * ql3;
            atomicAdd(&sm[SM_ES + l * 32 + r0 + i], pe);
        }
    }
    __syncthreads();

    if (tid < 32) {
        float e0 = sm[SM_ES + tid], e1 = sm[SM_ES + 32 + tid], e2 = sm[SM_ES + 64 + tid];
        float m  = fmaxf(e0, fmaxf(e1, e2));
        float a0 = expf(e0 - m), a1 = expf(e1 - m), a2 = expf(e2 - m);
        float s  = 1.0f / (a0 + a1 + a2);
        sm[SM_AL + tid]      = a0 * s;
        sm[SM_AL + 32 + tid] = a1 * s;
        sm[SM_AL + 64 + tid] = a2 * s;
    }
    __syncthreads();

    #pragma unroll
    for (int i = 0; i < 16; i++) {
        int idx = i * 256 + tid;
        int k = idx >> 5, r = idx & 31;
        float v = sm[SM_AL + r]      * sm[SM_E + (0 * 128 + k) * 36 + r]
                + sm[SM_AL + 32 + r] * sm[SM_E + (1 * 128 + k) * 36 + r]
                + sm[SM_AL + 64 + r] * sm[SM_E + (2 * 128 + k) * 36 + r];
        sm[SM_P + k * 36 + r] = v;
    }
    __syncthreads();

    {
        const int o0 = tt * 2;
        float a0 = 0, a1 = 0, b0 = 0, b1 = 0, c0 = 0, c1 = 0, d0 = 0, d1 = 0;
        #pragma unroll 4
        for (int k = 0; k < 128; k++) {
            float4 p = *(const float4*)(sm + SM_P + k * 36 + r0);
            float2 w2 = *(const float2*)(sm + SM_OW + k * 66 + o0);
            a0 += p.x * w2.x; a1 += p.x * w2.y;
            b0 += p.y * w2.x; b1 += p.y * w2.y;
            c0 += p.z * w2.x; c1 += p.z * w2.y;
            d0 += p.w * w2.x; d1 += p.w * w2.y;
        }
        float ob0 = ob[o0], ob1 = ob[o0 + 1];
        int row = blk * 32 + r0;
        out[(size_t)(row + 0) * OUTD + o0]     = a0 + ob0;
        out[(size_t)(row + 0) * OUTD + o0 + 1] = a1 + ob1;
        out[(size_t)(row + 1) * OUTD + o0]     = b0 + ob0;
        out[(size_t)(row + 1) * OUTD + o0 + 1] = b1 + ob1;
        out[(size_t)(row + 2) * OUTD + o0]     = c0 + ob0;
        out[(size_t)(row + 2) * OUTD + o0 + 1] = c1 + ob1;
        out[(size_t)(row + 3) * OUTD + o0]     = d0 + ob0;
        out[(size_t)(row + 3) * OUTD + o0 + 1] = d1 + ob1;
    }
}

// ---------------- launch -----------------------------------------------------
extern "C" void kernel_launch(void* const* d_in, const int* in_sizes, int n_in,
                              void* d_out, int out_size) {
    const float* x     = (const float*)d_in[0];
    const int*   ei    = (const int*)  d_in[1];
    const int*   dp    = (const int*)  d_in[2];
    const int*   tp    = (const int*)  d_in[3];
    const int*   dn    = (const int*)  d_in[4];
    const int*   tn    = (const int*)  d_in[5];
    const float* w0    = (const float*)d_in[7];
    const float* b0    = (const float*)d_in[8];
    const float* w1    = (const float*)d_in[9];
    const float* b1    = (const float*)d_in[10];
    const float* w2    = (const float*)d_in[11];
    const float* b2    = (const float*)d_in[12];
    const float* gamma = (const float*)d_in[13];
    const float* beta  = (const float*)d_in[14];
    const float* WD    = (const float*)d_in[15];
    const float* WT    = (const float*)d_in[16];
    const float* qD    = (const float*)d_in[17];
    const float* qT    = (const float*)d_in[18];
    const float* ow    = (const float*)d_in[19];
    const float* ob    = (const float*)d_in[20];
    float*       out   = (float*)d_out;

    const int* src = ei;
    const int* dst = ei + NE;

    float* accBase = nullptr;
    cudaGetSymbolAddress((void**)&accBase, g_accL);
    float* statsBase = nullptr;
    cudaGetSymbolAddress((void**)&statsBase, g_stats);

    static bool attr_done = false;
    if (!attr_done) {
        cudaFuncSetAttribute(k_att, cudaFuncAttributeMaxDynamicSharedMemorySize,
                             SM_FLOATS * (int)sizeof(float));
        attr_done = true;
    }

    const int GEMM_BLOCKS = (NN + 127) / 128;        // 391
    const int AGG_BLOCKS  = NN / 8;                  // 6250 (exact)

    float* acc0 = accBase;
    float* acc1 = accBase + (size_t)NN * HID;
    float* acc2 = accBase + (size_t)2 * NN * HID;
    float* st0 = statsBase;
    float* st1 = statsBase + 2 * HID;
    float* st2 = statsBase + 4 * HID;

    // Launch order chosen so layer-0 GEMM is the 4th launch (ncu capture slot).
    k_init     <<<(NN + 255) / 256, 256>>>();
    k_deg_count<<<(NE + 255) / 256, 256>>>(dst);
    k_scan     <<<1, 1024>>>();
    k_gemm<IND, false><<<GEMM_BLOCKS, 256>>>(x, w0, nullptr, nullptr, nullptr);
    k_scatter  <<<(NE + 255) / 256, 256>>>(src, dst);
    k_agg      <<<AGG_BLOCKS, 256>>>(b0, acc0, st0);

    k_gemm<HID, true><<<GEMM_BLOCKS, 256>>>(acc0, w1, st0, gamma, beta);
    k_agg      <<<AGG_BLOCKS, 256>>>(b1, acc1, st1);

    k_gemm<HID, true><<<GEMM_BLOCKS, 256>>>(acc1, w2, st1, gamma, beta);
    k_agg      <<<AGG_BLOCKS, 256>>>(b2, acc2, st2);

    k_att<<<512, 256, SM_FLOATS * (int)sizeof(float)>>>(dp, tp, dn, tn, WD, WT,
                                                        qD, qT, ow, ob,
                                                        gamma, beta, out);
}